// round 15
// baseline (speedup 1.0000x reference)
#include <cuda_runtime.h>
#include <cstdint>

// FullAttention causal, BH=32, S=2048, D=64, fp32 in/out.
// Portable-ISA tensor-core flash attention:
//   QK^T in 2xTF32 (Q split hi/lo via RZ bit-mask; K raw fp32, HW-truncated),
//   PV in plain tf32 (P bit-masked to match HW truncation exactly),
//   cp.async double-buffered K/V, unshifted softmax p = exp2(s*log2e).
// R14: kk-granular softmax/PV pipeline (softmax n-blocks k+2..k+3 overlap
//      PV kk..kk+1) with V fragments still loaded once; branchless masks.

#define S_LEN   2048
#define HEAD_D  64
#define BM      128
#define BN      64
#define NBH     32
#define QTILES  (S_LEN / BM)        // 16
#define NTHREADS 128
#define NWARPS  4                   // 32 q rows per warp (2 row-blocks of 16)

// smem strides (floats) chosen for conflict-free fragment access
#define KS 68
#define VS 72
#define PS 68

// float offsets inside dynamic smem
#define OFF_K  0                    // 2 x 64*KS  = 8704
#define OFF_V  8704                 // 2 x 64*VS  = 9216
#define OFF_P  17920                // 128*PS     = 8704 (also Q staging)
#define SMEM_FLOATS 26624
#define SMEM_BYTES  (SMEM_FLOATS * 4)   // 106496  (x2 CTAs = 212992 <= ~228KB/SM)

#define LOG2E   1.4426950408889634f
#define QSCALE  (0.125f * LOG2E)
#define TF32_MASK 0xFFFFE000u

static __device__ __forceinline__ uint32_t smem_u32(const void* p) {
    uint32_t a;
    asm("{ .reg .u64 t; cvta.to.shared.u64 t, %1; cvt.u32.u64 %0, t; }" : "=r"(a) : "l"(p));
    return a;
}

#define CP_ASYNC16(sa, gp) \
    asm volatile("cp.async.cg.shared.global [%0], [%1], 16;" :: "r"(sa), "l"(gp) : "memory")
#define CP_COMMIT() asm volatile("cp.async.commit_group;" ::: "memory")
#define CP_WAIT0()  asm volatile("cp.async.wait_group 0;" ::: "memory")

static __device__ __forceinline__ float ex2_approx(float x) {
    float r;
    asm("ex2.approx.ftz.f32 %0, %1;" : "=f"(r) : "f"(x));
    return r;
}
// RZ-truncate to tf32 bit pattern (exactly what the MMA HW does to operands)
static __device__ __forceinline__ float tf32_rz(float x) {
    return __uint_as_float(__float_as_uint(x) & TF32_MASK);
}

static __device__ __forceinline__ void mma_tf32(float d[4], const uint32_t a[4],
                                                uint32_t b0, uint32_t b1) {
    asm volatile(
        "mma.sync.aligned.m16n8k8.row.col.f32.tf32.tf32.f32 "
        "{%0,%1,%2,%3}, {%4,%5,%6,%7}, {%8,%9}, {%0,%1,%2,%3};"
        : "+f"(d[0]), "+f"(d[1]), "+f"(d[2]), "+f"(d[3])
        : "r"(a[0]), "r"(a[1]), "r"(a[2]), "r"(a[3]), "r"(b0), "r"(b1));
}

__global__ void __launch_bounds__(NTHREADS, 2)
fa_mma_kernel(const float* __restrict__ q, const float* __restrict__ k,
              const float* __restrict__ v, float* __restrict__ out) {
    extern __shared__ float smem[];
    float* sK = smem + OFF_K;
    float* sV = smem + OFF_V;
    float* sP = smem + OFF_P;

    const int tid = threadIdx.x;
    const int w   = tid >> 5;
    const int lid = tid & 31;
    const int g   = lid >> 2;      // groupID 0..7
    const int tg  = lid & 3;       // thread-in-group 0..3

    const int bid = blockIdx.x;
    const int qt  = (QTILES - 1) - (bid >> 5);   // heavy q-tiles first
    const int bh  = bid & 31;
    const int qbase = qt * BM;
    const int T     = 2 * (qt + 1);              // KV tiles of 64

    const float* qg = q + ((size_t)bh * S_LEN + qbase) * HEAD_D;
    const float* kg = k + (size_t)bh * S_LEN * HEAD_D;
    const float* vg = v + (size_t)bh * S_LEN * HEAD_D;

    // ---- prefetch KV tile 0 (cp.async): 64 rows x 16 float4 each ----
    {
        const uint32_t skb = smem_u32(sK);
        const uint32_t svb = smem_u32(sV);
#pragma unroll
        for (int p = 0; p < 8; ++p) {
            int idx = p * NTHREADS + tid;
            int r = idx >> 4, c4 = idx & 15;
            CP_ASYNC16(skb + (uint32_t)(r * KS + c4 * 4) * 4u,
                       (const char*)(kg + (size_t)r * HEAD_D + c4 * 4));
            CP_ASYNC16(svb + (uint32_t)(r * VS + c4 * 4) * 4u,
                       (const char*)(vg + (size_t)r * HEAD_D + c4 * 4));
        }
        CP_COMMIT();
    }

    // ---- stage Q (scaled by 0.125*log2e) into sP ----
    {
#pragma unroll
        for (int p = 0; p < 16; ++p) {           // 128 rows x 16 f4 / 128 thr
            int idx = p * NTHREADS + tid;
            int r = idx >> 4, c4 = idx & 15;
            float4 f = ((const float4*)qg)[idx];
            float4* dst = (float4*)(sP + r * PS + c4 * 4);
            *dst = make_float4(f.x * QSCALE, f.y * QSCALE, f.z * QSCALE, f.w * QSCALE);
        }
    }
    __syncthreads();

    // A-fragments for 2 row-blocks: rows w*32 + rb*16 + {g, g+8}
    float qf[2][8][4];
#pragma unroll
    for (int rb = 0; rb < 2; ++rb) {
        const float* base = sP + (w * 32 + rb * 16 + g) * PS;
#pragma unroll
        for (int kk = 0; kk < 8; ++kk) {
            qf[rb][kk][0] = base[kk * 8 + tg];
            qf[rb][kk][1] = base[8 * PS + kk * 8 + tg];
            qf[rb][kk][2] = base[kk * 8 + tg + 4];
            qf[rb][kk][3] = base[8 * PS + kk * 8 + tg + 4];
        }
    }

    // P row bases (also used as pa sources in PV)
    float* prow0 = sP + (w * 32 + g) * PS;       // rb0 rows
    float* prow1 = prow0 + 16 * PS;              // rb1 rows

    float oa[2][8][4];
#pragma unroll
    for (int rb = 0; rb < 2; ++rb)
#pragma unroll
        for (int n = 0; n < 8; ++n)
            oa[rb][n][0] = oa[rb][n][1] = oa[rb][n][2] = oa[rb][n][3] = 0.f;
    float lsum[2][2] = {{0.f, 0.f}, {0.f, 0.f}};

    for (int t = 0; t < T; ++t) {
        CP_WAIT0();            // this thread's copies for tile t complete
        __syncthreads();       // all threads' copies visible; prior tile fully read

        // issue prefetch for tile t+1 (flies during compute of tile t)
        if (t + 1 < T) {
            const int kv1 = (t + 1) * BN;
            const uint32_t skb = smem_u32(sK + ((t + 1) & 1) * (64 * KS));
            const uint32_t svb = smem_u32(sV + ((t + 1) & 1) * (64 * VS));
#pragma unroll
            for (int p = 0; p < 8; ++p) {
                int idx = p * NTHREADS + tid;
                int r = idx >> 4, c4 = idx & 15;
                CP_ASYNC16(skb + (uint32_t)(r * KS + c4 * 4) * 4u,
                           (const char*)(kg + (size_t)(kv1 + r) * HEAD_D + c4 * 4));
                CP_ASYNC16(svb + (uint32_t)(r * VS + c4 * 4) * 4u,
                           (const char*)(vg + (size_t)(kv1 + r) * HEAD_D + c4 * 4));
            }
            CP_COMMIT();
        }

        // diagonal tile: warps 0-1 (rows entirely above the diagonal) -> skip
        if (t == T - 1 && w < 2) continue;
        const bool need_mask = (t == T - 1) || (t == T - 2 && w < 2);

        const float* K0 = sK + (t & 1) * (64 * KS);
        const float* V0 = sV + (t & 1) * (64 * VS);

        // ---- S = Q K^T in 2xTF32: per kk, hi sweep then lo sweep, both blocks ----
        float sacc[2][8][4];
#pragma unroll
        for (int rb = 0; rb < 2; ++rb)
#pragma unroll
            for (int n = 0; n < 8; ++n)
                sacc[rb][n][0] = sacc[rb][n][1] = sacc[rb][n][2] = sacc[rb][n][3] = 0.f;
#pragma unroll
        for (int kk = 0; kk < 8; ++kk) {
            // RZ hi/lo split of both blocks' Q fragments (LOP3 + FSUB, no cvt)
            uint32_t uqh[2][4], uql[2][4];
#pragma unroll
            for (int rb = 0; rb < 2; ++rb)
#pragma unroll
                for (int i = 0; i < 4; ++i) {
                    uint32_t uh = __float_as_uint(qf[rb][kk][i]) & TF32_MASK;
                    uqh[rb][i] = uh;
                    uql[rb][i] = __float_as_uint(qf[rb][kk][i] - __uint_as_float(uh));
                }
            // load all 8 b-fragments once (K raw fp32: MMA HW truncates to tf32)
            uint32_t b[8][2];
            const float* krow = K0 + g * KS + kk * 8 + tg;
#pragma unroll
            for (int n = 0; n < 8; ++n) {
                b[n][0] = __float_as_uint(krow[n * 8 * KS]);
                b[n][1] = __float_as_uint(krow[n * 8 * KS + 4]);
            }
#pragma unroll
            for (int n = 0; n < 8; ++n) {
                mma_tf32(sacc[0][n], uqh[0], b[n][0], b[n][1]);
                mma_tf32(sacc[1][n], uqh[1], b[n][0], b[n][1]);
            }
#pragma unroll
            for (int n = 0; n < 8; ++n) {
                mma_tf32(sacc[0][n], uql[0], b[n][0], b[n][1]);
                mma_tf32(sacc[1][n], uql[1], b[n][0], b[n][1]);
            }
        }

        // ---- softmax/PV pipeline ----
        const int kv0 = t * BN;
        // branchless mask limits (INT_MAX when no masking needed)
        int limA[2], limB[2];
#pragma unroll
        for (int rb = 0; rb < 2; ++rb) {
            const int row_lo = qbase + w * 32 + rb * 16 + g;
            limA[rb] = need_mask ? row_lo : 0x7FFFFFFF;
            limB[rb] = need_mask ? row_lo + 8 : 0x7FFFFFFF;
        }

// softmax of one n-block for one row-block: p = exp2(s), RZ->tf32, write P
#define SOFTMAX_NB(rb, n)                                                           \
        {                                                                           \
            float* pr = (rb) ? prow1 : prow0;                                       \
            const int col0 = kv0 + (n) * 8 + 2 * tg;                                \
            const int col1 = col0 + 1;                                              \
            float p00 = (col0 <= limA[rb]) ? tf32_rz(ex2_approx(sacc[rb][n][0])) : 0.f; \
            float p01 = (col1 <= limA[rb]) ? tf32_rz(ex2_approx(sacc[rb][n][1])) : 0.f; \
            float p10 = (col0 <= limB[rb]) ? tf32_rz(ex2_approx(sacc[rb][n][2])) : 0.f; \
            float p11 = (col1 <= limB[rb]) ? tf32_rz(ex2_approx(sacc[rb][n][3])) : 0.f; \
            lsum[rb][0] += p00 + p01;                                               \
            lsum[rb][1] += p10 + p11;                                               \
            *(float2*)(pr + (n) * 8 + 2 * tg) = make_float2(p00, p01);              \
            *(float2*)(pr + 8 * PS + (n) * 8 + 2 * tg) = make_float2(p10, p11);     \
        }

// PV step kk for both row-blocks; V fragments loaded once
#define PV_KK(kk)                                                                   \
        {                                                                           \
            uint32_t pa0[4], pa1[4];                                                \
            pa0[0] = __float_as_uint(prow0[(kk) * 8 + tg]);                         \
            pa0[1] = __float_as_uint(prow0[8 * PS + (kk) * 8 + tg]);                \
            pa0[2] = __float_as_uint(prow0[(kk) * 8 + tg + 4]);                     \
            pa0[3] = __float_as_uint(prow0[8 * PS + (kk) * 8 + tg + 4]);            \
            pa1[0] = __float_as_uint(prow1[(kk) * 8 + tg]);                         \
            pa1[1] = __float_as_uint(prow1[8 * PS + (kk) * 8 + tg]);                \
            pa1[2] = __float_as_uint(prow1[(kk) * 8 + tg + 4]);                     \
            pa1[3] = __float_as_uint(prow1[8 * PS + (kk) * 8 + tg + 4]);            \
            const float* vrow = V0 + ((kk) * 8 + tg) * VS + g;                      \
            uint32_t vb[8][2];                                                      \
            _Pragma("unroll")                                                       \
            for (int n = 0; n < 8; ++n) {                                           \
                vb[n][0] = __float_as_uint(vrow[n * 8]);                            \
                vb[n][1] = __float_as_uint(vrow[4 * VS + n * 8]);                   \
            }                                                                       \
            _Pragma("unroll")                                                       \
            for (int n = 0; n < 8; ++n) {                                           \
                mma_tf32(oa[0][n], pa0, vb[n][0], vb[n][1]);                        \
                mma_tf32(oa[1][n], pa1, vb[n][0], vb[n][1]);                        \
            }                                                                       \
        }

        // prologue: n-blocks 0,1
        SOFTMAX_NB(0, 0) SOFTMAX_NB(1, 0) SOFTMAX_NB(0, 1) SOFTMAX_NB(1, 1)
        __syncwarp();
        // fused chunks: softmax n+2..n+3 overlaps PV kk..kk+1 (disjoint P cols)
        SOFTMAX_NB(0, 2) SOFTMAX_NB(1, 2) PV_KK(0)
        SOFTMAX_NB(0, 3) SOFTMAX_NB(1, 3) PV_KK(1)
        __syncwarp();
        SOFTMAX_NB(0, 4) SOFTMAX_NB(1, 4) PV_KK(2)
        SOFTMAX_NB(0, 5) SOFTMAX_NB(1, 5) PV_KK(3)
        __syncwarp();
        SOFTMAX_NB(0, 6) SOFTMAX_NB(1, 6) PV_KK(4)
        SOFTMAX_NB(0, 7) SOFTMAX_NB(1, 7) PV_KK(5)
        __syncwarp();
        PV_KK(6) PV_KK(7)
    }

    // ---- rowsum reduce across the 4 lanes of each row, normalize, store ----
#pragma unroll
    for (int rb = 0; rb < 2; ++rb) {
        lsum[rb][0] += __shfl_xor_sync(0xffffffffu, lsum[rb][0], 1);
        lsum[rb][0] += __shfl_xor_sync(0xffffffffu, lsum[rb][0], 2);
        lsum[rb][1] += __shfl_xor_sync(0xffffffffu, lsum[rb][1], 1);
        lsum[rb][1] += __shfl_xor_sync(0xffffffffu, lsum[rb][1], 2);
        const float inv0 = 1.0f / lsum[rb][0];
        const float inv1 = 1.0f / lsum[rb][1];
        const int row_lo = qbase + w * 32 + rb * 16 + g;
        float* o_lo = out + ((size_t)bh * S_LEN + row_lo) * HEAD_D;
        float* o_hi = o_lo + 8 * HEAD_D;
#pragma unroll
        for (int n = 0; n < 8; ++n) {
            *(float2*)(o_lo + n * 8 + 2 * tg) =
                make_float2(oa[rb][n][0] * inv0, oa[rb][n][1] * inv0);
            *(float2*)(o_hi + n * 8 + 2 * tg) =
                make_float2(oa[rb][n][2] * inv1, oa[rb][n][3] * inv1);
        }
    }
}

extern "C" void kernel_launch(void* const* d_in, const int* in_sizes, int n_in,
                              void* d_out, int out_size) {
    (void)in_sizes; (void)n_in; (void)out_size;
    const float* q = (const float*)d_in[0];
    const float* k = (const float*)d_in[1];
    const float* v = (const float*)d_in[2];
    float* out = (float*)d_out;

    cudaFuncSetAttribute(fa_mma_kernel,
                         cudaFuncAttributeMaxDynamicSharedMemorySize, SMEM_BYTES);
    fa_mma_kernel<<<QTILES * NBH, NTHREADS, SMEM_BYTES>>>(q, k, v, out);
}

// round 17
// speedup vs baseline: 1.5943x; 1.5943x over previous
#include <cuda_runtime.h>
#include <cstdint>

// FullAttention causal, BH=32, S=2048, D=64, fp32 in/out.
// Portable-ISA tensor-core flash attention:
//   QK^T in 1xTF32 with truncation-bias correction folded into QSCALE,
//   PV in plain tf32 with V-truncation bias correction folded into epilogue,
//   P RZ-masked for exact numerator/denominator consistency,
//   cp.async double-buffered K/V, unshifted softmax p = exp2(s*log2e).
// R16 = R15 resubmitted (prior round failed on infra, not kernel).

#define S_LEN   2048
#define HEAD_D  64
#define BM      128
#define BN      64
#define NBH     32
#define QTILES  (S_LEN / BM)        // 16
#define NTHREADS 128
#define NWARPS  4                   // 32 q rows per warp (2 row-blocks of 16)

// smem strides (floats) chosen for conflict-free fragment access
#define KS 68
#define VS 72
#define PS 68

// float offsets inside dynamic smem
#define OFF_K  0                    // 2 x 64*KS  = 8704
#define OFF_V  8704                 // 2 x 64*VS  = 9216
#define OFF_P  17920                // 128*PS     = 8704 (also Q staging)
#define SMEM_FLOATS 26624
#define SMEM_BYTES  (SMEM_FLOATS * 4)   // 106496  (x2 CTAs = 212992 <= ~228KB/SM)

#define LOG2E   1.4426950408889634f
// bias correction: q and k are each RZ-truncated (mean factor 1-2^-11 each)
#define QSCALE  (0.125f * LOG2E * (1.0f + 0.0009765625f))   // *(1+2^-10)
// V RZ-truncation bias: output uniformly scaled by ~(1-2^-11)
#define OCORR   (1.0f + 4.8828125e-4f)                      // (1+2^-11)
#define TF32_MASK 0xFFFFE000u

static __device__ __forceinline__ uint32_t smem_u32(const void* p) {
    uint32_t a;
    asm("{ .reg .u64 t; cvta.to.shared.u64 t, %1; cvt.u32.u64 %0, t; }" : "=r"(a) : "l"(p));
    return a;
}

#define CP_ASYNC16(sa, gp) \
    asm volatile("cp.async.cg.shared.global [%0], [%1], 16;" :: "r"(sa), "l"(gp) : "memory")
#define CP_COMMIT() asm volatile("cp.async.commit_group;" ::: "memory")
#define CP_WAIT0()  asm volatile("cp.async.wait_group 0;" ::: "memory")

static __device__ __forceinline__ float ex2_approx(float x) {
    float r;
    asm("ex2.approx.ftz.f32 %0, %1;" : "=f"(r) : "f"(x));
    return r;
}
// RZ-truncate to tf32 bit pattern (exactly what the MMA HW does to operands)
static __device__ __forceinline__ float tf32_rz(float x) {
    return __uint_as_float(__float_as_uint(x) & TF32_MASK);
}

static __device__ __forceinline__ void mma_tf32(float d[4], const uint32_t a[4],
                                                uint32_t b0, uint32_t b1) {
    asm volatile(
        "mma.sync.aligned.m16n8k8.row.col.f32.tf32.tf32.f32 "
        "{%0,%1,%2,%3}, {%4,%5,%6,%7}, {%8,%9}, {%0,%1,%2,%3};"
        : "+f"(d[0]), "+f"(d[1]), "+f"(d[2]), "+f"(d[3])
        : "r"(a[0]), "r"(a[1]), "r"(a[2]), "r"(a[3]), "r"(b0), "r"(b1));
}

__global__ void __launch_bounds__(NTHREADS, 2)
fa_mma_kernel(const float* __restrict__ q, const float* __restrict__ k,
              const float* __restrict__ v, float* __restrict__ out) {
    extern __shared__ float smem[];
    float* sK = smem + OFF_K;
    float* sV = smem + OFF_V;
    float* sP = smem + OFF_P;

    const int tid = threadIdx.x;
    const int w   = tid >> 5;
    const int lid = tid & 31;
    const int g   = lid >> 2;      // groupID 0..7
    const int tg  = lid & 3;       // thread-in-group 0..3

    const int bid = blockIdx.x;
    const int qt  = (QTILES - 1) - (bid >> 5);   // heavy q-tiles first
    const int bh  = bid & 31;
    const int qbase = qt * BM;
    const int T     = 2 * (qt + 1);              // KV tiles of 64

    const float* qg = q + ((size_t)bh * S_LEN + qbase) * HEAD_D;
    const float* kg = k + (size_t)bh * S_LEN * HEAD_D;
    const float* vg = v + (size_t)bh * S_LEN * HEAD_D;

    // ---- prefetch KV tile 0 (cp.async): 64 rows x 16 float4 each ----
    {
        const uint32_t skb = smem_u32(sK);
        const uint32_t svb = smem_u32(sV);
#pragma unroll
        for (int p = 0; p < 8; ++p) {
            int idx = p * NTHREADS + tid;
            int r = idx >> 4, c4 = idx & 15;
            CP_ASYNC16(skb + (uint32_t)(r * KS + c4 * 4) * 4u,
                       (const char*)(kg + (size_t)r * HEAD_D + c4 * 4));
            CP_ASYNC16(svb + (uint32_t)(r * VS + c4 * 4) * 4u,
                       (const char*)(vg + (size_t)r * HEAD_D + c4 * 4));
        }
        CP_COMMIT();
    }

    // ---- stage Q (scaled by QSCALE incl. bias correction) into sP ----
    {
#pragma unroll
        for (int p = 0; p < 16; ++p) {           // 128 rows x 16 f4 / 128 thr
            int idx = p * NTHREADS + tid;
            int r = idx >> 4, c4 = idx & 15;
            float4 f = ((const float4*)qg)[idx];
            float4* dst = (float4*)(sP + r * PS + c4 * 4);
            *dst = make_float4(f.x * QSCALE, f.y * QSCALE, f.z * QSCALE, f.w * QSCALE);
        }
    }
    __syncthreads();

    // A-fragments (raw fp32 bits; MMA HW truncates to tf32) for 2 row-blocks
    uint32_t qfu[2][8][4];
#pragma unroll
    for (int rb = 0; rb < 2; ++rb) {
        const float* base = sP + (w * 32 + rb * 16 + g) * PS;
#pragma unroll
        for (int kk = 0; kk < 8; ++kk) {
            qfu[rb][kk][0] = __float_as_uint(base[kk * 8 + tg]);
            qfu[rb][kk][1] = __float_as_uint(base[8 * PS + kk * 8 + tg]);
            qfu[rb][kk][2] = __float_as_uint(base[kk * 8 + tg + 4]);
            qfu[rb][kk][3] = __float_as_uint(base[8 * PS + kk * 8 + tg + 4]);
        }
    }

    float oa[2][8][4];
#pragma unroll
    for (int rb = 0; rb < 2; ++rb)
#pragma unroll
        for (int n = 0; n < 8; ++n)
            oa[rb][n][0] = oa[rb][n][1] = oa[rb][n][2] = oa[rb][n][3] = 0.f;
    float lsum[2][2] = {{0.f, 0.f}, {0.f, 0.f}};

    for (int t = 0; t < T; ++t) {
        CP_WAIT0();            // this thread's copies for tile t complete
        __syncthreads();       // all threads' copies visible; prior tile fully read

        // issue prefetch for tile t+1 (flies during compute of tile t)
        if (t + 1 < T) {
            const int kv1 = (t + 1) * BN;
            const uint32_t skb = smem_u32(sK + ((t + 1) & 1) * (64 * KS));
            const uint32_t svb = smem_u32(sV + ((t + 1) & 1) * (64 * VS));
#pragma unroll
            for (int p = 0; p < 8; ++p) {
                int idx = p * NTHREADS + tid;
                int r = idx >> 4, c4 = idx & 15;
                CP_ASYNC16(skb + (uint32_t)(r * KS + c4 * 4) * 4u,
                           (const char*)(kg + (size_t)(kv1 + r) * HEAD_D + c4 * 4));
                CP_ASYNC16(svb + (uint32_t)(r * VS + c4 * 4) * 4u,
                           (const char*)(vg + (size_t)(kv1 + r) * HEAD_D + c4 * 4));
            }
            CP_COMMIT();
        }

        // diagonal tile: warps 0-1 (rows entirely above the diagonal) -> skip
        if (t == T - 1 && w < 2) continue;
        const bool need_mask = (t == T - 1) || (t == T - 2 && w < 2);

        const float* K0 = sK + (t & 1) * (64 * KS);
        const float* V0 = sV + (t & 1) * (64 * VS);

        // ---- S = Q K^T in 1xTF32 (raw operands, HW truncation, bias-corrected) ----
        float sacc[2][8][4];
#pragma unroll
        for (int rb = 0; rb < 2; ++rb)
#pragma unroll
            for (int n = 0; n < 8; ++n)
                sacc[rb][n][0] = sacc[rb][n][1] = sacc[rb][n][2] = sacc[rb][n][3] = 0.f;
#pragma unroll
        for (int kk = 0; kk < 8; ++kk) {
            // load all 8 b-fragments once (K raw fp32: MMA HW truncates to tf32)
            uint32_t b[8][2];
            const float* krow = K0 + g * KS + kk * 8 + tg;
#pragma unroll
            for (int n = 0; n < 8; ++n) {
                b[n][0] = __float_as_uint(krow[n * 8 * KS]);
                b[n][1] = __float_as_uint(krow[n * 8 * KS + 4]);
            }
#pragma unroll
            for (int n = 0; n < 8; ++n) {
                mma_tf32(sacc[0][n], qfu[0][kk], b[n][0], b[n][1]);
                mma_tf32(sacc[1][n], qfu[1][kk], b[n][0], b[n][1]);
            }
        }

        // ---- softmax rb: p = exp2(s) (no shift; s bounded), P tf32-RZ -> sP ----
        const int kv0 = t * BN;
#define SOFTMAX_RB(rb)                                                              \
        {                                                                           \
            float* prow_lo = sP + (w * 32 + (rb) * 16 + g) * PS;                    \
            float* prow_hi = prow_lo + 8 * PS;                                      \
            if (!need_mask) {                                                       \
                _Pragma("unroll")                                                   \
                for (int n = 0; n < 8; ++n) {                                       \
                    float p00 = tf32_rz(ex2_approx(sacc[rb][n][0]));                \
                    float p01 = tf32_rz(ex2_approx(sacc[rb][n][1]));                \
                    float p10 = tf32_rz(ex2_approx(sacc[rb][n][2]));                \
                    float p11 = tf32_rz(ex2_approx(sacc[rb][n][3]));                \
                    lsum[rb][0] += p00 + p01;                                       \
                    lsum[rb][1] += p10 + p11;                                       \
                    *(float2*)(prow_lo + n * 8 + 2 * tg) = make_float2(p00, p01);   \
                    *(float2*)(prow_hi + n * 8 + 2 * tg) = make_float2(p10, p11);   \
                }                                                                   \
            } else {                                                                \
                const int row_lo = qbase + w * 32 + (rb) * 16 + g;                  \
                const int row_hi = row_lo + 8;                                      \
                _Pragma("unroll")                                                   \
                for (int n = 0; n < 8; ++n) {                                       \
                    const int col0 = kv0 + n * 8 + 2 * tg;                          \
                    const int col1 = col0 + 1;                                      \
                    float p00 = (col0 <= row_lo) ? tf32_rz(ex2_approx(sacc[rb][n][0])) : 0.f; \
                    float p01 = (col1 <= row_lo) ? tf32_rz(ex2_approx(sacc[rb][n][1])) : 0.f; \
                    float p10 = (col0 <= row_hi) ? tf32_rz(ex2_approx(sacc[rb][n][2])) : 0.f; \
                    float p11 = (col1 <= row_hi) ? tf32_rz(ex2_approx(sacc[rb][n][3])) : 0.f; \
                    lsum[rb][0] += p00 + p01;                                       \
                    lsum[rb][1] += p10 + p11;                                       \
                    *(float2*)(prow_lo + n * 8 + 2 * tg) = make_float2(p00, p01);   \
                    *(float2*)(prow_hi + n * 8 + 2 * tg) = make_float2(p10, p11);   \
                }                                                                   \
            }                                                                       \
        }

        SOFTMAX_RB(0)
        SOFTMAX_RB(1)
        __syncwarp();

        // ---- O += P V, both row-blocks share each V fragment (loaded once) ----
        {
            const float* pb0 = sP + (w * 32 + g) * PS;
            const float* pb1 = pb0 + 16 * PS;
#pragma unroll
            for (int kk = 0; kk < 8; ++kk) {
                uint32_t pa0[4], pa1[4];
                pa0[0] = __float_as_uint(pb0[kk * 8 + tg]);
                pa0[1] = __float_as_uint(pb0[8 * PS + kk * 8 + tg]);
                pa0[2] = __float_as_uint(pb0[kk * 8 + tg + 4]);
                pa0[3] = __float_as_uint(pb0[8 * PS + kk * 8 + tg + 4]);
                pa1[0] = __float_as_uint(pb1[kk * 8 + tg]);
                pa1[1] = __float_as_uint(pb1[8 * PS + kk * 8 + tg]);
                pa1[2] = __float_as_uint(pb1[kk * 8 + tg + 4]);
                pa1[3] = __float_as_uint(pb1[8 * PS + kk * 8 + tg + 4]);
                const float* vrow = V0 + (kk * 8 + tg) * VS + g;
                uint32_t b[8][2];
#pragma unroll
                for (int n = 0; n < 8; ++n) {
                    b[n][0] = __float_as_uint(vrow[n * 8]);
                    b[n][1] = __float_as_uint(vrow[4 * VS + n * 8]);
                }
#pragma unroll
                for (int n = 0; n < 8; ++n) {
                    mma_tf32(oa[0][n], pa0, b[n][0], b[n][1]);
                    mma_tf32(oa[1][n], pa1, b[n][0], b[n][1]);
                }
            }
        }
    }

    // ---- rowsum reduce, normalize (V-truncation bias corrected), store ----
#pragma unroll
    for (int rb = 0; rb < 2; ++rb) {
        lsum[rb][0] += __shfl_xor_sync(0xffffffffu, lsum[rb][0], 1);
        lsum[rb][0] += __shfl_xor_sync(0xffffffffu, lsum[rb][0], 2);
        lsum[rb][1] += __shfl_xor_sync(0xffffffffu, lsum[rb][1], 1);
        lsum[rb][1] += __shfl_xor_sync(0xffffffffu, lsum[rb][1], 2);
        const float inv0 = OCORR / lsum[rb][0];
        const float inv1 = OCORR / lsum[rb][1];
        const int row_lo = qbase + w * 32 + rb * 16 + g;
        float* o_lo = out + ((size_t)bh * S_LEN + row_lo) * HEAD_D;
        float* o_hi = o_lo + 8 * HEAD_D;
#pragma unroll
        for (int n = 0; n < 8; ++n) {
            *(float2*)(o_lo + n * 8 + 2 * tg) =
                make_float2(oa[rb][n][0] * inv0, oa[rb][n][1] * inv0);
            *(float2*)(o_hi + n * 8 + 2 * tg) =
                make_float2(oa[rb][n][2] * inv1, oa[rb][n][3] * inv1);
        }
    }
}

extern "C" void kernel_launch(void* const* d_in, const int* in_sizes, int n_in,
                              void* d_out, int out_size) {
    (void)in_sizes; (void)n_in; (void)out_size;
    const float* q = (const float*)d_in[0];
    const float* k = (const float*)d_in[1];
    const float* v = (const float*)d_in[2];
    float* out = (float*)d_out;

    cudaFuncSetAttribute(fa_mma_kernel,
                         cudaFuncAttributeMaxDynamicSharedMemorySize, SMEM_BYTES);
    fa_mma_kernel<<<QTILES * NBH, NTHREADS, SMEM_BYTES>>>(q, k, v, out);
}